// round 13
// baseline (speedup 1.0000x reference)
#include <cuda_runtime.h>

// JaggedConv2D: per-channel depthwise conv, ragged odd kernels 5..29 centered
// in 29x29 window, SAME padding. B=4, C=128, H=W=256, fp32.
//
// R13 (base: R12, 363us / best R11 359us): amortize fill epochs.
//  - TH 64->128, RY=2 (rows r and r+64): blocks halve, fill/output -15%,
//    fill fraction per block ~halves (biggest win on small-K channels)
//  - RX=16 row-mapped compute (R12), full-row vin, 4-tap weight broadcasts
//  - lane<->row mapping + SW/4 odd -> conflict-free LDS.128
//  - vectorized divide-free fill (R11), aligned-floor vin addressing
//  - accumulation order identical -> bit-identical results

#define BB 4
#define CC 128
#define HH 256
#define WW 256
#define KMAXSZ 29

#define TW 64
#define TH 128
#define RX 16
#define RY 2
#define NTH 256

#define WSTRIDE 32
#define WT_OFF  (WSTRIDE * KMAXSZ)   // 928 floats (128B aligned)

template<int K>
__device__ __forceinline__ void conv_body(const float* __restrict__ x,
                                          const float* __restrict__ kern,
                                          float* __restrict__ out,
                                          int ch, int b, float* smem)
{
    constexpr int HALO  = K / 2;
    constexpr int HALO4 = (HALO + 3) & ~3;   // 4-aligned left halo
    constexpr int D     = HALO4 - HALO;      // column shift (0..3)
    constexpr int OFF   = D;                 // register shift (base aligned)
    constexpr int IH    = TH + K - 1;
    constexpr int IW    = TW + K - 1 + D;
    constexpr int NVC   = (OFF + K - 1 + RX - 1) / 4 + 1;   // vin float4 count
    constexpr int NG    = (K + 3) / 4;                      // 4-tap weight groups
    constexpr int REACH = (TW - RX) + 4 * NVC;
    constexpr int SW0   = (((IW > REACH) ? IW : REACH) + 3) & ~3;
    constexpr int SW    = ((SW0 >> 2) & 1) ? SW0 : SW0 + 4;  // SW/4 odd
    constexpr int SW4   = SW / 4;
    constexpr int S     = (KMAXSZ - K) / 2;

    float* sWt = smem;            // [K][WSTRIDE]
    float* sIn = smem + WT_OFF;   // [IH][SW], base 128B aligned

    const int tid = threadIdx.x;
    const int tileX0 = blockIdx.x * TW;
    const int tileY0 = blockIdx.y * TH;

    // ---- weights: ragged KxK window -> stride-32 rows, zero padded ----
    const float* kbase = kern + (size_t)ch * KMAXSZ * KMAXSZ;
    #pragma unroll 1
    for (int i = tid; i < K * WSTRIDE; i += NTH) {
        int ky = i >> 5, kx = i & 31;
        float v = 0.0f;
        if (kx < K)
            v = kbase[(S + ky) * KMAXSZ + (S + kx)];
        sWt[i] = v;
    }

    // ---- input tile (+halo), vectorized row fill, zero padded ----
    // smem col c holds global x = tileX0 - HALO4 + c (4-aligned origin)
    {
        const float* xbase = x + (size_t)(b * CC + ch) * HH * WW;
        const int inY0 = tileY0 - HALO;
        const int inX0 = tileX0 - HALO4;
        const int lane = tid & 31;
        const int warp = tid >> 5;

        if (lane < SW4) {
            const int gx0 = inX0 + lane * 4;                 // 4-aligned
            const bool xfast = (gx0 >= 0) && (gx0 + 4 <= WW);
            #pragma unroll 1
            for (int rb = warp; rb < IH; rb += 32) {
                float4 v[4];
                #pragma unroll
                for (int u = 0; u < 4; u++) {
                    int r = rb + 8 * u;
                    v[u].x = 0.f; v[u].y = 0.f; v[u].z = 0.f; v[u].w = 0.f;
                    int gy = inY0 + r;
                    if (r < IH && (unsigned)gy < (unsigned)HH) {
                        const float* gp = xbase + (size_t)gy * WW + gx0;
                        if (xfast) {
                            v[u] = *reinterpret_cast<const float4*>(gp);
                        } else {
                            if ((unsigned)(gx0 + 0) < (unsigned)WW) v[u].x = gp[0];
                            if ((unsigned)(gx0 + 1) < (unsigned)WW) v[u].y = gp[1];
                            if ((unsigned)(gx0 + 2) < (unsigned)WW) v[u].z = gp[2];
                            if ((unsigned)(gx0 + 3) < (unsigned)WW) v[u].w = gp[3];
                        }
                    }
                }
                #pragma unroll
                for (int u = 0; u < 4; u++) {
                    int r = rb + 8 * u;
                    if (r < IH)
                        *reinterpret_cast<float4*>(&sIn[r * SW + lane * 4]) = v[u];
                }
            }
        }
    }
    __syncthreads();

    // ---- lane<->row mapping: warp w -> tx=w&3, row=(w>>2)*32+lane ----
    // thread computes rows {row, row+64} x cols [c0, c0+16)
    // quarter-warp = 8 consecutive rows, SW/4 odd -> conflict-free LDS.128
    const int lane = tid & 31;
    const int warp = tid >> 5;
    const int tx   = warp & 3;
    const int row  = (warp >> 2) * 32 + lane;   // 0..63
    const int c0   = tx * RX;                   // 64B aligned

    float acc[RY][RX];
    #pragma unroll
    for (int i = 0; i < RY; i++)
        #pragma unroll
        for (int j = 0; j < RX; j++)
            acc[i][j] = 0.0f;

    #pragma unroll 1
    for (int ky = 0; ky < K; ky++) {
        const float* wr = &sWt[ky * WSTRIDE];

        #pragma unroll
        for (int i = 0; i < RY; i++) {
            // full-row input window: NVC aligned float4 loads
            const float* rp = &sIn[(row + 64 * i + ky) * SW + c0];  // 16B aligned
            float vin[NVC * 4];
            #pragma unroll
            for (int t = 0; t < NVC; t++) {
                float4 q = *reinterpret_cast<const float4*>(rp + 4 * t);
                vin[4*t+0] = q.x; vin[4*t+1] = q.y;
                vin[4*t+2] = q.z; vin[4*t+3] = q.w;
            }

            #pragma unroll
            for (int g = 0; g < NG; g++) {
                float4 wq = *reinterpret_cast<const float4*>(wr + 4 * g);
                float w4[4] = {wq.x, wq.y, wq.z, wq.w};
                #pragma unroll
                for (int t = 0; t < 4; t++) {
                    if (4 * g + t < K) {
                        #pragma unroll
                        for (int j = 0; j < RX; j++)
                            acc[i][j] = fmaf(w4[t], vin[OFF + 4 * g + t + j],
                                             acc[i][j]);
                    }
                }
            }
        }
    }

    // ---- store: 4 float4 per row, 2 rows per thread ----
    float* obase = out + (size_t)(b * CC + ch) * HH * WW;
    #pragma unroll
    for (int i = 0; i < RY; i++) {
        float* op = &obase[(size_t)(tileY0 + row + 64 * i) * WW + tileX0 + c0];
        #pragma unroll
        for (int t = 0; t < 4; t++) {
            float4 v;
            v.x = acc[i][4*t+0]; v.y = acc[i][4*t+1];
            v.z = acc[i][4*t+2]; v.w = acc[i][4*t+3];
            *reinterpret_cast<float4*>(op + 4 * t) = v;
        }
    }
}

__global__ __launch_bounds__(NTH, 3)
void jagged_conv(const float* __restrict__ x,
                 const float* __restrict__ kern,
                 float* __restrict__ out)
{
    extern __shared__ float smem[];
    const int z  = blockIdx.z;
    const int ch = (CC - 1) - (z >> 2);   // descending K: big kernels first
    const int b  = z & 3;

    // k_i = floor(5 + 24*i/127), forced odd (matches np.linspace/astype)
    int k = 5 + (24 * ch) / 127;
    if ((k & 1) == 0) k -= 1;

    switch (k) {
        case  5: conv_body< 5>(x, kern, out, ch, b, smem); break;
        case  7: conv_body< 7>(x, kern, out, ch, b, smem); break;
        case  9: conv_body< 9>(x, kern, out, ch, b, smem); break;
        case 11: conv_body<11>(x, kern, out, ch, b, smem); break;
        case 13: conv_body<13>(x, kern, out, ch, b, smem); break;
        case 15: conv_body<15>(x, kern, out, ch, b, smem); break;
        case 17: conv_body<17>(x, kern, out, ch, b, smem); break;
        case 19: conv_body<19>(x, kern, out, ch, b, smem); break;
        case 21: conv_body<21>(x, kern, out, ch, b, smem); break;
        case 23: conv_body<23>(x, kern, out, ch, b, smem); break;
        case 25: conv_body<25>(x, kern, out, ch, b, smem); break;
        case 27: conv_body<27>(x, kern, out, ch, b, smem); break;
        case 29: conv_body<29>(x, kern, out, ch, b, smem); break;
        default: break;
    }
}

extern "C" void kernel_launch(void* const* d_in, const int* in_sizes, int n_in,
                              void* d_out, int out_size)
{
    (void)in_sizes; (void)n_in; (void)out_size;
    const float* x    = (const float*)d_in[0];
    const float* kern = (const float*)d_in[1];
    float* out        = (float*)d_out;

    // max smem across K: K=29 -> WT_OFF(928) + IH(156)*SW(100) = 16528 floats
    const int smem_bytes = (WT_OFF + 156 * 100) * (int)sizeof(float);
    cudaFuncSetAttribute(jagged_conv,
                         cudaFuncAttributeMaxDynamicSharedMemorySize, smem_bytes);

    dim3 grid(WW / TW, HH / TH, BB * CC);
    dim3 block(NTH, 1, 1);
    jagged_conv<<<grid, block, smem_bytes>>>(x, kern, out);
}

// round 14
// speedup vs baseline: 1.0490x; 1.0490x over previous
#include <cuda_runtime.h>

// JaggedConv2D: per-channel depthwise conv, ragged odd kernels 5..29 centered
// in 29x29 window, SAME padding. B=4, C=128, H=W=256, fp32.
//
// R14 (base: R11 = 359us best): cp.async fill.
//  - fill uses cp.async.cg (LDGSTS) 16B chunks: no register round-trip,
//    single commit/wait -> one exposed DRAM latency per block (was ~3)
//  - 4-aligned tile x-origin makes boundary handling exact: chunk fully OOB
//    -> src-size 0 (HW zero-fill); right edge -> src-size tail zero-fill
//  - compute identical to R11: 16-tap weight chunks, aligned-floor vin,
//    parity-pair conflict-free LDS.128 (SW/4 odd) -> bit-identical output

#define BB 4
#define CC 128
#define HH 256
#define WW 256
#define KMAXSZ 29

#define TW 64
#define TH 64
#define RX 8
#define RY 2
#define NTH 256

#define WSTRIDE 32
#define WT_OFF  (WSTRIDE * KMAXSZ)   // 928 floats (128B aligned)

__device__ __forceinline__ void cp_async16(unsigned smem_addr,
                                           const void* gptr, int src_size)
{
    asm volatile("cp.async.cg.shared.global [%0], [%1], 16, %2;"
                 :: "r"(smem_addr), "l"(gptr), "r"(src_size));
}

template<int K, int KXO, int SW, int D>
__device__ __forceinline__ void do_chunk(const float* __restrict__ sWtRow,
                                         const float* __restrict__ sIn,
                                         int rowBase, int c0,
                                         float acc[RY][RX])
{
    constexpr int KW   = (K - KXO < 16) ? (K - KXO) : 16;   // taps this chunk
    constexpr int NW4  = (KW + 3) / 4;                      // weight float4s
    constexpr int AOFF = (D + KXO) & ~3;                    // aligned smem offset
    constexpr int OFF  = (D + KXO) & 3;                     // register shift
    constexpr int NVC  = (OFF + KW + RX - 1 + 3) / 4;       // vin float4s

    // weights: uniform address across warp -> broadcast
    float w[NW4 * 4];
    #pragma unroll
    for (int t = 0; t < NW4; t++) {
        float4 q = *reinterpret_cast<const float4*>(sWtRow + KXO + 4 * t);
        w[4*t+0] = q.x; w[4*t+1] = q.y; w[4*t+2] = q.z; w[4*t+3] = q.w;
    }

    #pragma unroll
    for (int i = 0; i < RY; i++) {
        const float* rp = &sIn[(rowBase + 2 * i) * SW + c0 + AOFF];  // 16B aligned
        float vin[NVC * 4];
        #pragma unroll
        for (int t = 0; t < NVC; t++) {
            float4 q = *reinterpret_cast<const float4*>(rp + 4 * t);
            vin[4*t+0] = q.x; vin[4*t+1] = q.y;
            vin[4*t+2] = q.z; vin[4*t+3] = q.w;
        }
        #pragma unroll
        for (int kx = 0; kx < KW; kx++)
            #pragma unroll
            for (int j = 0; j < RX; j++)
                acc[i][j] = fmaf(w[kx], vin[OFF + kx + j], acc[i][j]);
    }
}

template<int K>
__device__ __forceinline__ void conv_body(const float* __restrict__ x,
                                          const float* __restrict__ kern,
                                          float* __restrict__ out,
                                          int ch, int b, float* smem)
{
    constexpr int HALO  = K / 2;
    constexpr int HALO4 = (HALO + 3) & ~3;   // 4-aligned left halo
    constexpr int D     = HALO4 - HALO;      // logical column shift (0..3)
    constexpr int IH    = TH + K - 1;
    constexpr int IW    = TW + K - 1 + D;
    constexpr int KW0   = (K < 16) ? K : 16;
    constexpr int R0    = 4 * (((D & 3) + KW0 + RX - 1 + 3) / 4);
    constexpr int KW1   = (K > 16) ? (K - 16) : 0;
    constexpr int R1    = (K > 16)
        ? (((D + 16) & ~3) + 4 * ((((D + 16) & 3) + KW1 + RX - 1 + 3) / 4))
        : 0;
    constexpr int RMAX  = (R0 > R1) ? R0 : R1;
    constexpr int REACH = (TW - RX) + RMAX;
    constexpr int SW0   = (((IW > REACH) ? IW : REACH) + 3) & ~3;
    constexpr int SW    = ((SW0 >> 2) & 1) ? SW0 : SW0 + 4;  // SW/4 odd
    constexpr int SW4   = SW / 4;
    constexpr int S     = (KMAXSZ - K) / 2;

    float* sWt = smem;            // [K][WSTRIDE]
    float* sIn = smem + WT_OFF;   // [IH][SW], base 128B aligned

    const int tid = threadIdx.x;
    const int tileX0 = blockIdx.x * TW;
    const int tileY0 = blockIdx.y * TH;

    // ---- input tile (+halo) via cp.async: zero-filled boundaries ----
    // smem col c holds global x = tileX0 - HALO4 + c (4-aligned origin)
    {
        const float* xbase = x + (size_t)(b * CC + ch) * HH * WW;
        const int inY0 = tileY0 - HALO;
        const int inX0 = tileX0 - HALO4;
        const int lane = tid & 31;
        const int warp = tid >> 5;

        if (lane < SW4) {
            const int gx0 = inX0 + lane * 4;                 // 4-aligned
            // bytes available from gx0 within the row: 0 if OOB left/right,
            // tail-clamped at the right edge
            int xb = 0;
            if (gx0 >= 0) {
                int rem = WW - gx0;
                xb = rem >= 4 ? 16 : (rem > 0 ? rem * 4 : 0);
            }
            #pragma unroll 1
            for (int rb = warp; rb < IH; rb += 8) {
                int gy = inY0 + rb;
                bool yok = (unsigned)gy < (unsigned)HH;
                const float* gp = xbase + (yok ? (size_t)gy * WW : 0)
                                + (gx0 >= 0 ? gx0 : 0);
                int sz = yok ? xb : 0;
                unsigned saddr = (unsigned)__cvta_generic_to_shared(
                                     &sIn[rb * SW + lane * 4]);
                cp_async16(saddr, gp, sz);
            }
        }
    }

    // ---- weights: ragged KxK window -> stride-32 rows, zero padded ----
    const float* kbase = kern + (size_t)ch * KMAXSZ * KMAXSZ;
    #pragma unroll 1
    for (int i = tid; i < K * WSTRIDE; i += NTH) {
        int ky = i >> 5, kx = i & 31;
        float v = 0.0f;
        if (kx < K)
            v = kbase[(S + ky) * KMAXSZ + (S + kx)];
        sWt[i] = v;
    }

    asm volatile("cp.async.commit_group;" ::: "memory");
    asm volatile("cp.async.wait_group 0;" ::: "memory");
    __syncthreads();

    // ---- conflict-free parity-pair lane mapping ----
    const int parity = tid & 1;
    const int tx     = (tid >> 1) & 7;
    const int rg     = tid >> 4;
    const int c0 = tx * RX;                  // output col, 32B aligned
    const int r0 = rg * 4 + parity;          // rows r0 + 2i, i=0..RY-1

    float acc[RY][RX];
    #pragma unroll
    for (int i = 0; i < RY; i++)
        #pragma unroll
        for (int j = 0; j < RX; j++)
            acc[i][j] = 0.0f;

    #pragma unroll 1
    for (int ky = 0; ky < K; ky++) {
        const float* sWtRow = &sWt[ky * WSTRIDE];
        const int rowBase = r0 + ky;
        do_chunk<K, 0, SW, D>(sWtRow, sIn, rowBase, c0, acc);
        if constexpr (K > 16)
            do_chunk<K, 16, SW, D>(sWtRow, sIn, rowBase, c0, acc);
    }

    // ---- store: two float4 per row per thread ----
    float* obase = out + (size_t)(b * CC + ch) * HH * WW;
    #pragma unroll
    for (int i = 0; i < RY; i++) {
        float* op = &obase[(size_t)(tileY0 + r0 + 2 * i) * WW + tileX0 + c0];
        float4 v0, v1;
        v0.x = acc[i][0]; v0.y = acc[i][1]; v0.z = acc[i][2]; v0.w = acc[i][3];
        v1.x = acc[i][4]; v1.y = acc[i][5]; v1.z = acc[i][6]; v1.w = acc[i][7];
        *reinterpret_cast<float4*>(op)     = v0;
        *reinterpret_cast<float4*>(op + 4) = v1;
    }
}

__global__ __launch_bounds__(NTH, 4)
void jagged_conv(const float* __restrict__ x,
                 const float* __restrict__ kern,
                 float* __restrict__ out)
{
    extern __shared__ float smem[];
    const int z  = blockIdx.z;
    const int ch = (CC - 1) - (z >> 2);   // descending K: big kernels first
    const int b  = z & 3;

    // k_i = floor(5 + 24*i/127), forced odd (matches np.linspace/astype)
    int k = 5 + (24 * ch) / 127;
    if ((k & 1) == 0) k -= 1;

    switch (k) {
        case  5: conv_body< 5>(x, kern, out, ch, b, smem); break;
        case  7: conv_body< 7>(x, kern, out, ch, b, smem); break;
        case  9: conv_body< 9>(x, kern, out, ch, b, smem); break;
        case 11: conv_body<11>(x, kern, out, ch, b, smem); break;
        case 13: conv_body<13>(x, kern, out, ch, b, smem); break;
        case 15: conv_body<15>(x, kern, out, ch, b, smem); break;
        case 17: conv_body<17>(x, kern, out, ch, b, smem); break;
        case 19: conv_body<19>(x, kern, out, ch, b, smem); break;
        case 21: conv_body<21>(x, kern, out, ch, b, smem); break;
        case 23: conv_body<23>(x, kern, out, ch, b, smem); break;
        case 25: conv_body<25>(x, kern, out, ch, b, smem); break;
        case 27: conv_body<27>(x, kern, out, ch, b, smem); break;
        case 29: conv_body<29>(x, kern, out, ch, b, smem); break;
        default: break;
    }
}

extern "C" void kernel_launch(void* const* d_in, const int* in_sizes, int n_in,
                              void* d_out, int out_size)
{
    (void)in_sizes; (void)n_in; (void)out_size;
    const float* x    = (const float*)d_in[0];
    const float* kern = (const float*)d_in[1];
    float* out        = (float*)d_out;

    // max smem across K: K=29 -> WT_OFF(928) + IH(92)*SW(100) = 10128 floats
    const int smem_bytes = (WT_OFF + 92 * 100) * (int)sizeof(float);
    cudaFuncSetAttribute(jagged_conv,
                         cudaFuncAttributeMaxDynamicSharedMemorySize, smem_bytes);

    dim3 grid(WW / TW, HH / TH, BB * CC);
    dim3 block(NTH, 1, 1);
    jagged_conv<<<grid, block, smem_bytes>>>(x, kern, out);
}